// round 9
// baseline (speedup 1.0000x reference)
#include <cuda_runtime.h>
#include <cstdint>

#define MAXN 4096

// Per-x-query: wa, wb, wc, bitcast(I)
__device__ float4 g_xw[MAXN];
// Permuted per-x-query table for the b4 kernel: wa, wb, wc, bitcast(I | off<<16)
__device__ float4 g_xwp[MAXN];
// Per-y-query: h0, h2, h1, h3*ratio
__device__ float4 g_yw[MAXN];
__device__ int    g_yJ[MAXN];

__device__ const int PERM24[24][4] = {
    {0,1,2,3},{0,1,3,2},{0,2,1,3},{0,2,3,1},{0,3,1,2},{0,3,2,1},
    {1,0,2,3},{1,0,3,2},{1,2,0,3},{1,2,3,0},{1,3,0,2},{1,3,2,0},
    {2,0,1,3},{2,0,3,1},{2,1,0,3},{2,1,3,0},{2,3,0,1},{2,3,1,0},
    {3,0,1,2},{3,0,2,1},{3,1,0,2},{3,1,2,0},{3,2,0,1},{3,2,1,0}
};

__device__ __forceinline__ int searchsorted_inner(const float* __restrict__ axis, float q, int n) {
    // searchsorted(axis[1:n-1], q, side='left'): smallest idx in [0, n-2] with axis[1+idx] >= q
    int lo = 0, hi = n - 2;
    while (lo < hi) {
        int mid = (lo + hi) >> 1;
        if (axis[1 + mid] < q) lo = mid + 1; else hi = mid;
    }
    return lo;
}

__global__ void precompute_weights(const float* __restrict__ xaxis,
                                   const float* __restrict__ yaxis,
                                   const float* __restrict__ xs,
                                   const float* __restrict__ ys,
                                   int n) {
    int k = blockIdx.x * blockDim.x + threadIdx.x;
    if (k >= n) return;

    // ---- x direction ----
    {
        float q = xs[k];
        int I = searchsorted_inner(xaxis, q, n);
        float x0 = xaxis[I];
        float x1 = xaxis[I + 1];
        int i2 = (I + 2 < n) ? I + 2 : n - 1;     // defensive clamp (domain keeps I+2 < n)
        float x2 = xaxis[i2];
        float dx = x1 - x0;
        float t  = (q - x0) / dx;
        float t2 = t * t, t3 = t2 * t;
        float h0 = 1.0f - 3.0f * t2 + 2.0f * t3;
        float h1 = t - 2.0f * t2 + t3;
        float h2 = 3.0f * t2 - 2.0f * t3;
        float h3 = t3 - t2;
        float r  = dx / (x2 - x1);
        float4 w;
        w.x = h0 - h1;               // weight on S[I]
        w.y = h1 + h2 - h3 * r;      // weight on S[I+1]
        w.z = h3 * r;                // weight on S[I+2]
        w.w = __int_as_float(I);
        g_xw[k] = w;
    }

    // ---- y direction ----
    {
        float q = ys[k];
        int J = searchsorted_inner(yaxis, q, n);
        float y0 = yaxis[J];
        float y1 = yaxis[J + 1];
        int j2 = (J + 2 < n) ? J + 2 : n - 1;
        float y2 = yaxis[j2];
        float dy = y1 - y0;
        float t  = (q - y0) / dy;
        float t2 = t * t, t3 = t2 * t;
        float h0 = 1.0f - 3.0f * t2 + 2.0f * t3;
        float h1 = t - 2.0f * t2 + t3;
        float h2 = 3.0f * t2 - 2.0f * t3;
        float h3 = t3 - t2;
        float r  = dy / (y2 - y1);
        float4 w;
        w.x = h0;        // weight on out[.., J]
        w.y = h2;        // weight on out[.., J+1]
        w.z = h1;        // weight on (S[J+1,k]-S[J,k])
        w.w = h3 * r;    // weight on (S[J+2,k]-S[J+1,k])
        g_yw[k] = w;
        g_yJ[k] = J;
    }
}

// Build, per query-warp of 32 columns, a lane<->column permutation:
//  - offsets assigned to each quarter-warp form a transversal mod 8
//    (rowC4 STS stays bank-conflict-free by construction)
//  - the gather residues (I mod 8) within each quarter-warp are balanced
//    greedily (choosing among 24 phase-assignments per offset class),
//    reducing LDS.128 gather bank-group conflicts.
// One thread handles one query-warp serially (tiny kernel).
__global__ void build_perm(int nwarps) {
    int w = blockIdx.x * blockDim.x + threadIdx.x;
    if (w >= nwarps) return;
    int base = w * 32;

    int Ii[32];
    for (int o = 0; o < 32; o++)
        Ii[o] = __float_as_int(g_xw[base + o].w);

    int cnt[4][8];
    for (int p = 0; p < 4; p++)
        for (int r = 0; r < 8; r++) cnt[p][r] = 0;
    int slotUsed[4] = {0, 0, 0, 0};
    int lane_of[32];

    for (int c = 0; c < 8; c++) {
        int o0 = c, o1 = c + 8, o2 = c + 16, o3 = c + 24;
        int r0 = Ii[o0] & 7, r1 = Ii[o1] & 7, r2 = Ii[o2] & 7, r3 = Ii[o3] & 7;
        int bestCost = 1 << 30, bp = 0;
        for (int pi = 0; pi < 24; pi++) {
            const int* P = PERM24[pi];
            int cost = cnt[P[0]][r0] + cnt[P[1]][r1] + cnt[P[2]][r2] + cnt[P[3]][r3];
            if (cost < bestCost) { bestCost = cost; bp = pi; }
        }
        const int* P = PERM24[bp];
        cnt[P[0]][r0]++; cnt[P[1]][r1]++; cnt[P[2]][r2]++; cnt[P[3]][r3]++;
        lane_of[o0] = P[0] * 8 + slotUsed[P[0]]++;
        lane_of[o1] = P[1] * 8 + slotUsed[P[1]]++;
        lane_of[o2] = P[2] * 8 + slotUsed[P[2]]++;
        lane_of[o3] = P[3] * 8 + slotUsed[P[3]]++;
    }

    for (int o = 0; o < 32; o++) {
        float4 v = g_xw[base + o];
        int I = __float_as_int(v.w);
        v.w = __int_as_float(I | (o << 16));
        g_xwp[base + lane_of[o]] = v;
    }
}

// ─────────────── Specialized N=1024, 4-batches-per-CTA, batch-interleaved ───
// 512 threads/CTA, 2 position slots per thread. Columns are permuted within
// each query-warp per build_perm; the permuted column k is used consistently
// in staging, gather, D, and output, so all accesses stay sector-coalesced
// while the smem gather conflicts are minimized.
__global__ __launch_bounds__(512) void hermite2d_n1024_b4(
    const float* __restrict__ signal,
    float* __restrict__ out) {
    __shared__ float4 rowC4[1024];         // 16 KB, batch-interleaved

    const int t  = threadIdx.x;            // 0..511
    const int bm = blockIdx.x;
    const int bq = bm >> 10;               // batch quad
    const int my = bm & 1023;

    const int    J  = g_yJ[my];
    const float4 yw = g_yw[my];

    // weight loads are independent of smem — issue before staging/barrier
    const float4 w0 = g_xwp[t];
    const float4 w1 = g_xwp[t + 512];
    const int pk0 = __float_as_int(w0.w);
    const int pk1 = __float_as_int(w1.w);
    const int I0 = pk0 & 0xFFFF;
    const int I1 = pk1 & 0xFFFF;
    const int k0 = (t & ~31) | (pk0 >> 16);           // permuted column, slot 0
    const int k1 = ((t + 512) & ~31) | (pk1 >> 16);   // permuted column, slot 1

    const float* __restrict__ base0 = signal + (((size_t)(4 * bq + 0) << 10) + (size_t)J) * 1024u;
    const float* __restrict__ base1 = base0 + (1u << 20);
    const float* __restrict__ base2 = base0 + (2u << 20);
    const float* __restrict__ base3 = base0 + (3u << 20);

    float D[4][2];                         // [bb][slot] coalesced y-slope term

    #pragma unroll
    for (int j = 0; j < 2; j++) {
        const int k = j ? k1 : k0;
        float4 C;
        {
            float a = base0[k], c = base0[1024 + k], e = base0[2048 + k];
            C.x = yw.x * a + yw.y * c;
            D[0][j] = yw.z * (c - a) + yw.w * (e - c);
        }
        {
            float a = base1[k], c = base1[1024 + k], e = base1[2048 + k];
            C.y = yw.x * a + yw.y * c;
            D[1][j] = yw.z * (c - a) + yw.w * (e - c);
        }
        {
            float a = base2[k], c = base2[1024 + k], e = base2[2048 + k];
            C.z = yw.x * a + yw.y * c;
            D[2][j] = yw.z * (c - a) + yw.w * (e - c);
        }
        {
            float a = base3[k], c = base3[1024 + k], e = base3[2048 + k];
            C.w = yw.x * a + yw.y * c;
            D[3][j] = yw.z * (c - a) + yw.w * (e - c);
        }
        rowC4[k] = C;                      // STS.128, conflict-free (transversal)
    }
    __syncthreads();

    float* __restrict__ o0 = out + (((size_t)(4 * bq + 0) << 10) + (size_t)my) * 1024u;
    float* __restrict__ o1 = o0 + (1u << 20);
    float* __restrict__ o2 = o0 + (2u << 20);
    float* __restrict__ o3 = o0 + (3u << 20);

    {
        const float4 p0 = rowC4[I0];
        const float4 p1 = rowC4[I0 + 1];
        const float4 p2 = rowC4[I0 + 2];
        o0[k0] = w0.x * p0.x + w0.y * p1.x + w0.z * p2.x + D[0][0];
        o1[k0] = w0.x * p0.y + w0.y * p1.y + w0.z * p2.y + D[1][0];
        o2[k0] = w0.x * p0.z + w0.y * p1.z + w0.z * p2.z + D[2][0];
        o3[k0] = w0.x * p0.w + w0.y * p1.w + w0.z * p2.w + D[3][0];
    }
    {
        const float4 p0 = rowC4[I1];
        const float4 p1 = rowC4[I1 + 1];
        const float4 p2 = rowC4[I1 + 2];
        o0[k1] = w1.x * p0.x + w1.y * p1.x + w1.z * p2.x + D[0][1];
        o1[k1] = w1.x * p0.y + w1.y * p1.y + w1.z * p2.y + D[1][1];
        o2[k1] = w1.x * p0.z + w1.y * p1.z + w1.z * p2.z + D[2][1];
        o3[k1] = w1.x * p0.w + w1.y * p1.w + w1.z * p2.w + D[3][1];
    }
}

// ─────────────── Specialized N=1024, 1 row per CTA (B % 4 != 0) ─────────────
__global__ __launch_bounds__(256) void hermite2d_n1024(
    const float* __restrict__ signal,
    float* __restrict__ out) {
    __shared__ float rowC[1024];

    const int t  = threadIdx.x;
    const int bm = blockIdx.x;
    const int b  = bm >> 10;
    const int my = bm & 1023;

    const int    J  = g_yJ[my];
    const float4 yw = g_yw[my];

    const float* __restrict__ base = signal + (((size_t)b << 10) + (size_t)J) * 1024u;

    float D[4];
    #pragma unroll
    for (int j = 0; j < 4; j++) {
        const int k = t + 256 * j;
        float a = base[k];
        float c = base[1024 + k];
        float e = base[2048 + k];
        rowC[k] = yw.x * a + yw.y * c;
        D[j]    = yw.z * (c - a) + yw.w * (e - c);
    }
    __syncthreads();

    float* __restrict__ orow = out + (((size_t)b << 10) + (size_t)my) * 1024u;
    #pragma unroll
    for (int j = 0; j < 4; j++) {
        const int k = t + 256 * j;
        const float4 w = g_xw[k];
        const int I = __float_as_int(w.w);
        orow[k] = w.x * rowC[I] + w.y * rowC[I + 1] + w.z * rowC[I + 2] + D[j];
    }
}

// ───────────────────────── Generic fallback (any n % 4 == 0) ─────────────────
__global__ __launch_bounds__(256) void hermite2d_generic(
    const float* __restrict__ signal,
    float* __restrict__ out,
    int n) {
    extern __shared__ float sm[];          // 2*n floats
    float* rowC = sm;
    float* rowD = sm + n;

    int bm = blockIdx.x;
    int b  = bm / n;
    int my = bm - b * n;

    int    J  = g_yJ[my];
    float4 yw = g_yw[my];

    const float* base = signal + ((size_t)b * n + J) * (size_t)n;
    int nv = n >> 2;
    const float4* srcJ  = reinterpret_cast<const float4*>(base);
    const float4* srcJ1 = reinterpret_cast<const float4*>(base + n);
    const float4* srcJ2 = reinterpret_cast<const float4*>(base + 2 * (size_t)n);
    float4* dstC = reinterpret_cast<float4*>(rowC);
    float4* dstD = reinterpret_cast<float4*>(rowD);
    for (int i = threadIdx.x; i < nv; i += blockDim.x) {
        float4 a = srcJ[i];
        float4 c = srcJ1[i];
        float4 e = srcJ2[i];
        float4 C, Dv;
        C.x = yw.x * a.x + yw.y * c.x;
        C.y = yw.x * a.y + yw.y * c.y;
        C.z = yw.x * a.z + yw.y * c.z;
        C.w = yw.x * a.w + yw.y * c.w;
        Dv.x = yw.z * (c.x - a.x) + yw.w * (e.x - c.x);
        Dv.y = yw.z * (c.y - a.y) + yw.w * (e.y - c.y);
        Dv.z = yw.z * (c.z - a.z) + yw.w * (e.z - c.z);
        Dv.w = yw.z * (c.w - a.w) + yw.w * (e.w - c.w);
        dstC[i] = C;
        dstD[i] = Dv;
    }
    __syncthreads();

    float* orow = out + ((size_t)b * n + my) * (size_t)n;
    for (int k = threadIdx.x; k < n; k += blockDim.x) {
        float4 xw = g_xw[k];
        int I = __float_as_int(xw.w);
        orow[k] = xw.x * rowC[I] + xw.y * rowC[I + 1] + xw.z * rowC[I + 2] + rowD[k];
    }
}

extern "C" void kernel_launch(void* const* d_in, const int* in_sizes, int n_in,
                              void* d_out, int out_size) {
    const float* xaxis  = (const float*)d_in[0];
    const float* yaxis  = (const float*)d_in[1];
    const float* signal = (const float*)d_in[2];
    const float* xs     = (const float*)d_in[3];
    const float* ys     = (const float*)d_in[4];
    float* out = (float*)d_out;

    int n = in_sizes[0];                 // N (square grid, Mx = My = N)
    int B = in_sizes[2] / (n * n);       // batch

    precompute_weights<<<(n + 255) / 256, 256>>>(xaxis, yaxis, xs, ys, n);

    if (n == 1024 && (B % 4) == 0) {
        build_perm<<<1, 32>>>(n / 32);
        hermite2d_n1024_b4<<<(B / 4) * n, 512>>>(signal, out);
    } else if (n == 1024) {
        hermite2d_n1024<<<B * n, 256>>>(signal, out);
    } else {
        size_t smem = 2 * (size_t)n * sizeof(float);
        hermite2d_generic<<<B * n, 256, smem>>>(signal, out, n);
    }
}

// round 10
// speedup vs baseline: 1.0357x; 1.0357x over previous
#include <cuda_runtime.h>
#include <cstdint>

#define MAXN 4096

// Per-x-query: wa, wb, wc, bitcast(I)
__device__ float4 g_xw[MAXN];
// Permuted per-x-query table for the b4 kernel: wa, wb, wc, bitcast(I | off<<16)
__device__ float4 g_xwp[MAXN];
// Per-y-query: h0, h2, h1, h3*ratio
__device__ float4 g_yw[MAXN];
__device__ int    g_yJ[MAXN];

__constant__ int cPERM24[24][4] = {
    {0,1,2,3},{0,1,3,2},{0,2,1,3},{0,2,3,1},{0,3,1,2},{0,3,2,1},
    {1,0,2,3},{1,0,3,2},{1,2,0,3},{1,2,3,0},{1,3,0,2},{1,3,2,0},
    {2,0,1,3},{2,0,3,1},{2,1,0,3},{2,1,3,0},{2,3,0,1},{2,3,1,0},
    {3,0,1,2},{3,0,2,1},{3,1,0,2},{3,1,2,0},{3,2,0,1},{3,2,1,0}
};

__device__ __forceinline__ int searchsorted_inner_sm(const float* axis, float q, int n) {
    // searchsorted(axis[1:n-1], q, side='left') on smem-staged axis
    int lo = 0, hi = n - 2;
    while (lo < hi) {
        int mid = (lo + hi) >> 1;
        if (axis[1 + mid] < q) lo = mid + 1; else hi = mid;
    }
    return lo;
}

// Fused setup: axes staged in smem (binary search = LDS chain, not DRAM chain),
// weights computed per thread, then threads 0..7 of each full block run the
// per-query-warp gather permutation with ALL scratch in shared memory.
__global__ void precompute_fused(const float* __restrict__ xaxis,
                                 const float* __restrict__ yaxis,
                                 const float* __restrict__ xs,
                                 const float* __restrict__ ys,
                                 int n, int do_perm) {
    extern __shared__ float sax[];         // 2*n floats: sx | sy
    float* sx = sax;
    float* sy = sax + n;
    __shared__ float4 sW[256];
    __shared__ int sCnt[8][4][8];
    __shared__ int sSlot[8][4];

    const int tid = threadIdx.x;
    const int k   = blockIdx.x * 256 + tid;

    for (int i = tid; i < n; i += 256) { sx[i] = xaxis[i]; sy[i] = yaxis[i]; }
    __syncthreads();

    if (k < n) {
        // ---- x direction ----
        {
            float q = xs[k];
            int I = searchsorted_inner_sm(sx, q, n);
            float x0 = sx[I];
            float x1 = sx[I + 1];
            int i2 = (I + 2 < n) ? I + 2 : n - 1;
            float x2 = sx[i2];
            float dx = x1 - x0;
            float t  = (q - x0) / dx;
            float t2 = t * t, t3 = t2 * t;
            float h0 = 1.0f - 3.0f * t2 + 2.0f * t3;
            float h1 = t - 2.0f * t2 + t3;
            float h2 = 3.0f * t2 - 2.0f * t3;
            float h3 = t3 - t2;
            float r  = dx / (x2 - x1);
            float4 w;
            w.x = h0 - h1;               // weight on S[I]
            w.y = h1 + h2 - h3 * r;      // weight on S[I+1]
            w.z = h3 * r;                // weight on S[I+2]
            w.w = __int_as_float(I);
            g_xw[k] = w;
            sW[tid] = w;
        }
        // ---- y direction ----
        {
            float q = ys[k];
            int J = searchsorted_inner_sm(sy, q, n);
            float y0 = sy[J];
            float y1 = sy[J + 1];
            int j2 = (J + 2 < n) ? J + 2 : n - 1;
            float y2 = sy[j2];
            float dy = y1 - y0;
            float t  = (q - y0) / dy;
            float t2 = t * t, t3 = t2 * t;
            float h0 = 1.0f - 3.0f * t2 + 2.0f * t3;
            float h1 = t - 2.0f * t2 + t3;
            float h2 = 3.0f * t2 - 2.0f * t3;
            float h3 = t3 - t2;
            float r  = dy / (y2 - y1);
            float4 w;
            w.x = h0;
            w.y = h2;
            w.z = h1;
            w.w = h3 * r;
            g_yw[k] = w;
            g_yJ[k] = J;
        }
    }
    __syncthreads();

    // Per-query-warp permutation: offsets per quarter-warp form a transversal
    // mod 8 (STS conflict-free) while balancing gather residues I mod 8.
    if (do_perm && tid < 8 && blockIdx.x * 256 + 255 < n) {
        const int lbase = tid * 32;                 // within sW
        const int gbase = blockIdx.x * 256 + lbase; // within g_xwp
        #pragma unroll
        for (int p = 0; p < 4; p++) {
            sSlot[tid][p] = 0;
            #pragma unroll
            for (int r = 0; r < 8; r++) sCnt[tid][p][r] = 0;
        }
        for (int c = 0; c < 8; c++) {
            float4 v0 = sW[lbase + c];
            float4 v1 = sW[lbase + c + 8];
            float4 v2 = sW[lbase + c + 16];
            float4 v3 = sW[lbase + c + 24];
            int r0 = __float_as_int(v0.w) & 7;
            int r1 = __float_as_int(v1.w) & 7;
            int r2 = __float_as_int(v2.w) & 7;
            int r3 = __float_as_int(v3.w) & 7;
            int bestCost = 1 << 30, bp = 0;
            for (int pi = 0; pi < 24; pi++) {
                int cost = sCnt[tid][cPERM24[pi][0]][r0]
                         + sCnt[tid][cPERM24[pi][1]][r1]
                         + sCnt[tid][cPERM24[pi][2]][r2]
                         + sCnt[tid][cPERM24[pi][3]][r3];
                if (cost < bestCost) { bestCost = cost; bp = pi; }
            }
            int p0 = cPERM24[bp][0], p1 = cPERM24[bp][1];
            int p2 = cPERM24[bp][2], p3 = cPERM24[bp][3];
            sCnt[tid][p0][r0]++; sCnt[tid][p1][r1]++;
            sCnt[tid][p2][r2]++; sCnt[tid][p3][r3]++;
            int l0 = p0 * 8 + sSlot[tid][p0]++;
            int l1 = p1 * 8 + sSlot[tid][p1]++;
            int l2 = p2 * 8 + sSlot[tid][p2]++;
            int l3 = p3 * 8 + sSlot[tid][p3]++;
            v0.w = __int_as_float((__float_as_int(v0.w) & 0xFFFF) | ((c)      << 16));
            v1.w = __int_as_float((__float_as_int(v1.w) & 0xFFFF) | ((c + 8)  << 16));
            v2.w = __int_as_float((__float_as_int(v2.w) & 0xFFFF) | ((c + 16) << 16));
            v3.w = __int_as_float((__float_as_int(v3.w) & 0xFFFF) | ((c + 24) << 16));
            g_xwp[gbase + l0] = v0;
            g_xwp[gbase + l1] = v1;
            g_xwp[gbase + l2] = v2;
            g_xwp[gbase + l3] = v3;
        }
    }
}

// ─────────────── Specialized N=1024, 4-batches-per-CTA, batch-interleaved ───
// 512 threads/CTA, 2 position slots per thread. Columns are permuted within
// each query-warp; the permuted column k is used consistently in staging,
// gather, D, and output, so all accesses stay sector-coalesced while smem
// gather conflicts are minimized.
__global__ __launch_bounds__(512) void hermite2d_n1024_b4(
    const float* __restrict__ signal,
    float* __restrict__ out) {
    __shared__ float4 rowC4[1024];         // 16 KB, batch-interleaved

    const int t  = threadIdx.x;            // 0..511
    const int bm = blockIdx.x;
    const int bq = bm >> 10;               // batch quad
    const int my = bm & 1023;

    const int    J  = g_yJ[my];
    const float4 yw = g_yw[my];

    // weight loads are independent of smem — issue before staging/barrier
    const float4 w0 = g_xwp[t];
    const float4 w1 = g_xwp[t + 512];
    const int pk0 = __float_as_int(w0.w);
    const int pk1 = __float_as_int(w1.w);
    const int I0 = pk0 & 0xFFFF;
    const int I1 = pk1 & 0xFFFF;
    const int k0 = (t & ~31) | (pk0 >> 16);           // permuted column, slot 0
    const int k1 = ((t + 512) & ~31) | (pk1 >> 16);   // permuted column, slot 1

    const float* __restrict__ base0 = signal + (((size_t)(4 * bq + 0) << 10) + (size_t)J) * 1024u;
    const float* __restrict__ base1 = base0 + (1u << 20);
    const float* __restrict__ base2 = base0 + (2u << 20);
    const float* __restrict__ base3 = base0 + (3u << 20);

    float D[4][2];                         // [bb][slot] coalesced y-slope term

    #pragma unroll
    for (int j = 0; j < 2; j++) {
        const int k = j ? k1 : k0;
        float4 C;
        {
            float a = base0[k], c = base0[1024 + k], e = base0[2048 + k];
            C.x = yw.x * a + yw.y * c;
            D[0][j] = yw.z * (c - a) + yw.w * (e - c);
        }
        {
            float a = base1[k], c = base1[1024 + k], e = base1[2048 + k];
            C.y = yw.x * a + yw.y * c;
            D[1][j] = yw.z * (c - a) + yw.w * (e - c);
        }
        {
            float a = base2[k], c = base2[1024 + k], e = base2[2048 + k];
            C.z = yw.x * a + yw.y * c;
            D[2][j] = yw.z * (c - a) + yw.w * (e - c);
        }
        {
            float a = base3[k], c = base3[1024 + k], e = base3[2048 + k];
            C.w = yw.x * a + yw.y * c;
            D[3][j] = yw.z * (c - a) + yw.w * (e - c);
        }
        rowC4[k] = C;                      // STS.128, conflict-free (transversal)
    }
    __syncthreads();

    float* __restrict__ o0 = out + (((size_t)(4 * bq + 0) << 10) + (size_t)my) * 1024u;
    float* __restrict__ o1 = o0 + (1u << 20);
    float* __restrict__ o2 = o0 + (2u << 20);
    float* __restrict__ o3 = o0 + (3u << 20);

    {
        const float4 p0 = rowC4[I0];
        const float4 p1 = rowC4[I0 + 1];
        const float4 p2 = rowC4[I0 + 2];
        o0[k0] = w0.x * p0.x + w0.y * p1.x + w0.z * p2.x + D[0][0];
        o1[k0] = w0.x * p0.y + w0.y * p1.y + w0.z * p2.y + D[1][0];
        o2[k0] = w0.x * p0.z + w0.y * p1.z + w0.z * p2.z + D[2][0];
        o3[k0] = w0.x * p0.w + w0.y * p1.w + w0.z * p2.w + D[3][0];
    }
    {
        const float4 p0 = rowC4[I1];
        const float4 p1 = rowC4[I1 + 1];
        const float4 p2 = rowC4[I1 + 2];
        o0[k1] = w1.x * p0.x + w1.y * p1.x + w1.z * p2.x + D[0][1];
        o1[k1] = w1.x * p0.y + w1.y * p1.y + w1.z * p2.y + D[1][1];
        o2[k1] = w1.x * p0.z + w1.y * p1.z + w1.z * p2.z + D[2][1];
        o3[k1] = w1.x * p0.w + w1.y * p1.w + w1.z * p2.w + D[3][1];
    }
}

// ─────────────── Specialized N=1024, 1 row per CTA (B % 4 != 0) ─────────────
__global__ __launch_bounds__(256) void hermite2d_n1024(
    const float* __restrict__ signal,
    float* __restrict__ out) {
    __shared__ float rowC[1024];

    const int t  = threadIdx.x;
    const int bm = blockIdx.x;
    const int b  = bm >> 10;
    const int my = bm & 1023;

    const int    J  = g_yJ[my];
    const float4 yw = g_yw[my];

    const float* __restrict__ base = signal + (((size_t)b << 10) + (size_t)J) * 1024u;

    float D[4];
    #pragma unroll
    for (int j = 0; j < 4; j++) {
        const int k = t + 256 * j;
        float a = base[k];
        float c = base[1024 + k];
        float e = base[2048 + k];
        rowC[k] = yw.x * a + yw.y * c;
        D[j]    = yw.z * (c - a) + yw.w * (e - c);
    }
    __syncthreads();

    float* __restrict__ orow = out + (((size_t)b << 10) + (size_t)my) * 1024u;
    #pragma unroll
    for (int j = 0; j < 4; j++) {
        const int k = t + 256 * j;
        const float4 w = g_xw[k];
        const int I = __float_as_int(w.w);
        orow[k] = w.x * rowC[I] + w.y * rowC[I + 1] + w.z * rowC[I + 2] + D[j];
    }
}

// ───────────────────────── Generic fallback (any n % 4 == 0) ─────────────────
__global__ __launch_bounds__(256) void hermite2d_generic(
    const float* __restrict__ signal,
    float* __restrict__ out,
    int n) {
    extern __shared__ float sm[];          // 2*n floats
    float* rowC = sm;
    float* rowD = sm + n;

    int bm = blockIdx.x;
    int b  = bm / n;
    int my = bm - b * n;

    int    J  = g_yJ[my];
    float4 yw = g_yw[my];

    const float* base = signal + ((size_t)b * n + J) * (size_t)n;
    int nv = n >> 2;
    const float4* srcJ  = reinterpret_cast<const float4*>(base);
    const float4* srcJ1 = reinterpret_cast<const float4*>(base + n);
    const float4* srcJ2 = reinterpret_cast<const float4*>(base + 2 * (size_t)n);
    float4* dstC = reinterpret_cast<float4*>(rowC);
    float4* dstD = reinterpret_cast<float4*>(rowD);
    for (int i = threadIdx.x; i < nv; i += blockDim.x) {
        float4 a = srcJ[i];
        float4 c = srcJ1[i];
        float4 e = srcJ2[i];
        float4 C, Dv;
        C.x = yw.x * a.x + yw.y * c.x;
        C.y = yw.x * a.y + yw.y * c.y;
        C.z = yw.x * a.z + yw.y * c.z;
        C.w = yw.x * a.w + yw.y * c.w;
        Dv.x = yw.z * (c.x - a.x) + yw.w * (e.x - c.x);
        Dv.y = yw.z * (c.y - a.y) + yw.w * (e.y - c.y);
        Dv.z = yw.z * (c.z - a.z) + yw.w * (e.z - c.z);
        Dv.w = yw.z * (c.w - a.w) + yw.w * (e.w - c.w);
        dstC[i] = C;
        dstD[i] = Dv;
    }
    __syncthreads();

    float* orow = out + ((size_t)b * n + my) * (size_t)n;
    for (int k = threadIdx.x; k < n; k += blockDim.x) {
        float4 xw = g_xw[k];
        int I = __float_as_int(xw.w);
        orow[k] = xw.x * rowC[I] + xw.y * rowC[I + 1] + xw.z * rowC[I + 2] + rowD[k];
    }
}

extern "C" void kernel_launch(void* const* d_in, const int* in_sizes, int n_in,
                              void* d_out, int out_size) {
    const float* xaxis  = (const float*)d_in[0];
    const float* yaxis  = (const float*)d_in[1];
    const float* signal = (const float*)d_in[2];
    const float* xs     = (const float*)d_in[3];
    const float* ys     = (const float*)d_in[4];
    float* out = (float*)d_out;

    int n = in_sizes[0];                 // N (square grid, Mx = My = N)
    int B = in_sizes[2] / (n * n);       // batch

    int use_b4 = (n == 1024) && ((B % 4) == 0);
    size_t smem_pre = 2 * (size_t)n * sizeof(float);
    precompute_fused<<<(n + 255) / 256, 256, smem_pre>>>(xaxis, yaxis, xs, ys, n, use_b4);

    if (use_b4) {
        hermite2d_n1024_b4<<<(B / 4) * n, 512>>>(signal, out);
    } else if (n == 1024) {
        hermite2d_n1024<<<B * n, 256>>>(signal, out);
    } else {
        size_t smem = 2 * (size_t)n * sizeof(float);
        hermite2d_generic<<<B * n, 256, smem>>>(signal, out, n);
    }
}

// round 11
// speedup vs baseline: 1.3104x; 1.2653x over previous
#include <cuda_runtime.h>
#include <cstdint>

#define MAXN 4096

// Per-x-query: wa, wb, wc, bitcast(I)
__device__ float4 g_xw[MAXN];
// Per-y-query: h0, h2, h1, h3*ratio
__device__ float4 g_yw[MAXN];
__device__ int    g_yJ[MAXN];

__device__ __forceinline__ int searchsorted_inner_sm(const float* axis, float q, int n) {
    // searchsorted(axis[1:n-1], q, side='left') on smem-staged axis
    int lo = 0, hi = n - 2;
    while (lo < hi) {
        int mid = (lo + hi) >> 1;
        if (axis[1 + mid] < q) lo = mid + 1; else hi = mid;
    }
    return lo;
}

// Fused setup: axes staged in smem so the binary search is an LDS chain, not a
// DRAM-latency chain. One launch, ~2-3 us.
__global__ void precompute_fused(const float* __restrict__ xaxis,
                                 const float* __restrict__ yaxis,
                                 const float* __restrict__ xs,
                                 const float* __restrict__ ys,
                                 int n) {
    extern __shared__ float sax[];         // 2*n floats: sx | sy
    float* sx = sax;
    float* sy = sax + n;

    const int tid = threadIdx.x;
    const int k   = blockIdx.x * 256 + tid;

    for (int i = tid; i < n; i += 256) { sx[i] = xaxis[i]; sy[i] = yaxis[i]; }
    __syncthreads();

    if (k >= n) return;

    // ---- x direction ----
    {
        float q = xs[k];
        int I = searchsorted_inner_sm(sx, q, n);
        float x0 = sx[I];
        float x1 = sx[I + 1];
        int i2 = (I + 2 < n) ? I + 2 : n - 1;
        float x2 = sx[i2];
        float dx = x1 - x0;
        float t  = (q - x0) / dx;
        float t2 = t * t, t3 = t2 * t;
        float h0 = 1.0f - 3.0f * t2 + 2.0f * t3;
        float h1 = t - 2.0f * t2 + t3;
        float h2 = 3.0f * t2 - 2.0f * t3;
        float h3 = t3 - t2;
        float r  = dx / (x2 - x1);
        float4 w;
        w.x = h0 - h1;               // weight on S[I]
        w.y = h1 + h2 - h3 * r;      // weight on S[I+1]
        w.z = h3 * r;                // weight on S[I+2]
        w.w = __int_as_float(I);
        g_xw[k] = w;
    }
    // ---- y direction ----
    {
        float q = ys[k];
        int J = searchsorted_inner_sm(sy, q, n);
        float y0 = sy[J];
        float y1 = sy[J + 1];
        int j2 = (J + 2 < n) ? J + 2 : n - 1;
        float y2 = sy[j2];
        float dy = y1 - y0;
        float t  = (q - y0) / dy;
        float t2 = t * t, t3 = t2 * t;
        float h0 = 1.0f - 3.0f * t2 + 2.0f * t3;
        float h1 = t - 2.0f * t2 + t3;
        float h2 = 3.0f * t2 - 2.0f * t3;
        float h3 = t3 - t2;
        float r  = dy / (y2 - y1);
        float4 w;
        w.x = h0;        // weight on out[.., J]
        w.y = h2;        // weight on out[.., J+1]
        w.z = h1;        // weight on (S[J+1,k]-S[J,k])
        w.w = h3 * r;    // weight on (S[J+2,k]-S[J+1,k])
        g_yw[k] = w;
        g_yJ[k] = J;
    }
}

// ─────────────── Specialized N=1024, 4-batches-per-CTA, batch-interleaved ───
// 512 threads/CTA, 2 k-slots per thread (k = t, t+512). One CTA handles output
// row `my` for 4 consecutive batches. Smem is batch-interleaved:
// rowC4[i] = (C_b0[i], .., C_b3[i]) so one LDS.128 at tap i serves 4 batches.
// g_xw loads hoisted above the barrier to overlap their latency with staging.
__global__ __launch_bounds__(512) void hermite2d_n1024_b4(
    const float* __restrict__ signal,
    float* __restrict__ out) {
    __shared__ float4 rowC4[1024];         // 16 KB, batch-interleaved

    const int t  = threadIdx.x;            // 0..511
    const int bm = blockIdx.x;
    const int bq = bm >> 10;               // batch quad
    const int my = bm & 1023;

    const int    J  = g_yJ[my];
    const float4 yw = g_yw[my];

    // weight loads are independent of smem — issue before staging/barrier
    const float4 w0 = g_xw[t];
    const float4 w1 = g_xw[t + 512];

    const float* __restrict__ base0 = signal + (((size_t)(4 * bq + 0) << 10) + (size_t)J) * 1024u;
    const float* __restrict__ base1 = base0 + (1u << 20);
    const float* __restrict__ base2 = base0 + (2u << 20);
    const float* __restrict__ base3 = base0 + (3u << 20);

    float D[4][2];                         // [bb][j] coalesced y-slope term

    #pragma unroll
    for (int j = 0; j < 2; j++) {
        const int k = t + 512 * j;
        float4 C;
        {
            float a = base0[k], c = base0[1024 + k], e = base0[2048 + k];
            C.x = yw.x * a + yw.y * c;
            D[0][j] = yw.z * (c - a) + yw.w * (e - c);
        }
        {
            float a = base1[k], c = base1[1024 + k], e = base1[2048 + k];
            C.y = yw.x * a + yw.y * c;
            D[1][j] = yw.z * (c - a) + yw.w * (e - c);
        }
        {
            float a = base2[k], c = base2[1024 + k], e = base2[2048 + k];
            C.z = yw.x * a + yw.y * c;
            D[2][j] = yw.z * (c - a) + yw.w * (e - c);
        }
        {
            float a = base3[k], c = base3[1024 + k], e = base3[2048 + k];
            C.w = yw.x * a + yw.y * c;
            D[3][j] = yw.z * (c - a) + yw.w * (e - c);
        }
        rowC4[k] = C;                      // STS.128, conflict-free
    }
    __syncthreads();

    float* __restrict__ o0 = out + (((size_t)(4 * bq + 0) << 10) + (size_t)my) * 1024u;
    float* __restrict__ o1 = o0 + (1u << 20);
    float* __restrict__ o2 = o0 + (2u << 20);
    float* __restrict__ o3 = o0 + (3u << 20);

    {
        const int k = t;
        const int I = __float_as_int(w0.w);
        const float4 p0 = rowC4[I];
        const float4 p1 = rowC4[I + 1];
        const float4 p2 = rowC4[I + 2];
        o0[k] = w0.x * p0.x + w0.y * p1.x + w0.z * p2.x + D[0][0];
        o1[k] = w0.x * p0.y + w0.y * p1.y + w0.z * p2.y + D[1][0];
        o2[k] = w0.x * p0.z + w0.y * p1.z + w0.z * p2.z + D[2][0];
        o3[k] = w0.x * p0.w + w0.y * p1.w + w0.z * p2.w + D[3][0];
    }
    {
        const int k = t + 512;
        const int I = __float_as_int(w1.w);
        const float4 p0 = rowC4[I];
        const float4 p1 = rowC4[I + 1];
        const float4 p2 = rowC4[I + 2];
        o0[k] = w1.x * p0.x + w1.y * p1.x + w1.z * p2.x + D[0][1];
        o1[k] = w1.x * p0.y + w1.y * p1.y + w1.z * p2.y + D[1][1];
        o2[k] = w1.x * p0.z + w1.y * p1.z + w1.z * p2.z + D[2][1];
        o3[k] = w1.x * p0.w + w1.y * p1.w + w1.z * p2.w + D[3][1];
    }
}

// ─────────────── Specialized N=1024, 1 row per CTA (B % 4 != 0) ─────────────
__global__ __launch_bounds__(256) void hermite2d_n1024(
    const float* __restrict__ signal,
    float* __restrict__ out) {
    __shared__ float rowC[1024];

    const int t  = threadIdx.x;
    const int bm = blockIdx.x;
    const int b  = bm >> 10;
    const int my = bm & 1023;

    const int    J  = g_yJ[my];
    const float4 yw = g_yw[my];

    const float* __restrict__ base = signal + (((size_t)b << 10) + (size_t)J) * 1024u;

    float D[4];
    #pragma unroll
    for (int j = 0; j < 4; j++) {
        const int k = t + 256 * j;
        float a = base[k];
        float c = base[1024 + k];
        float e = base[2048 + k];
        rowC[k] = yw.x * a + yw.y * c;
        D[j]    = yw.z * (c - a) + yw.w * (e - c);
    }
    __syncthreads();

    float* __restrict__ orow = out + (((size_t)b << 10) + (size_t)my) * 1024u;
    #pragma unroll
    for (int j = 0; j < 4; j++) {
        const int k = t + 256 * j;
        const float4 w = g_xw[k];
        const int I = __float_as_int(w.w);
        orow[k] = w.x * rowC[I] + w.y * rowC[I + 1] + w.z * rowC[I + 2] + D[j];
    }
}

// ───────────────────────── Generic fallback (any n % 4 == 0) ─────────────────
__global__ __launch_bounds__(256) void hermite2d_generic(
    const float* __restrict__ signal,
    float* __restrict__ out,
    int n) {
    extern __shared__ float sm[];          // 2*n floats
    float* rowC = sm;
    float* rowD = sm + n;

    int bm = blockIdx.x;
    int b  = bm / n;
    int my = bm - b * n;

    int    J  = g_yJ[my];
    float4 yw = g_yw[my];

    const float* base = signal + ((size_t)b * n + J) * (size_t)n;
    int nv = n >> 2;
    const float4* srcJ  = reinterpret_cast<const float4*>(base);
    const float4* srcJ1 = reinterpret_cast<const float4*>(base + n);
    const float4* srcJ2 = reinterpret_cast<const float4*>(base + 2 * (size_t)n);
    float4* dstC = reinterpret_cast<float4*>(rowC);
    float4* dstD = reinterpret_cast<float4*>(rowD);
    for (int i = threadIdx.x; i < nv; i += blockDim.x) {
        float4 a = srcJ[i];
        float4 c = srcJ1[i];
        float4 e = srcJ2[i];
        float4 C, Dv;
        C.x = yw.x * a.x + yw.y * c.x;
        C.y = yw.x * a.y + yw.y * c.y;
        C.z = yw.x * a.z + yw.y * c.z;
        C.w = yw.x * a.w + yw.y * c.w;
        Dv.x = yw.z * (c.x - a.x) + yw.w * (e.x - c.x);
        Dv.y = yw.z * (c.y - a.y) + yw.w * (e.y - c.y);
        Dv.z = yw.z * (c.z - a.z) + yw.w * (e.z - c.z);
        Dv.w = yw.z * (c.w - a.w) + yw.w * (e.w - c.w);
        dstC[i] = C;
        dstD[i] = Dv;
    }
    __syncthreads();

    float* orow = out + ((size_t)b * n + my) * (size_t)n;
    for (int k = threadIdx.x; k < n; k += blockDim.x) {
        float4 xw = g_xw[k];
        int I = __float_as_int(xw.w);
        orow[k] = xw.x * rowC[I] + xw.y * rowC[I + 1] + xw.z * rowC[I + 2] + rowD[k];
    }
}

extern "C" void kernel_launch(void* const* d_in, const int* in_sizes, int n_in,
                              void* d_out, int out_size) {
    const float* xaxis  = (const float*)d_in[0];
    const float* yaxis  = (const float*)d_in[1];
    const float* signal = (const float*)d_in[2];
    const float* xs     = (const float*)d_in[3];
    const float* ys     = (const float*)d_in[4];
    float* out = (float*)d_out;

    int n = in_sizes[0];                 // N (square grid, Mx = My = N)
    int B = in_sizes[2] / (n * n);       // batch

    size_t smem_pre = 2 * (size_t)n * sizeof(float);
    precompute_fused<<<(n + 255) / 256, 256, smem_pre>>>(xaxis, yaxis, xs, ys, n);

    if (n == 1024 && (B % 4) == 0) {
        hermite2d_n1024_b4<<<(B / 4) * n, 512>>>(signal, out);
    } else if (n == 1024) {
        hermite2d_n1024<<<B * n, 256>>>(signal, out);
    } else {
        size_t smem = 2 * (size_t)n * sizeof(float);
        hermite2d_generic<<<B * n, 256, smem>>>(signal, out, n);
    }
}

// round 12
// speedup vs baseline: 1.4546x; 1.1100x over previous
#include <cuda_runtime.h>
#include <cuda_fp16.h>
#include <cstdint>

#define MAXN 4096

// Per-x-query: wa, wb, wc, bitcast(I)
__device__ float4 g_xw[MAXN];
// Per-y-query: h0, h2, h1, h3*ratio
__device__ float4 g_yw[MAXN];
__device__ int    g_yJ[MAXN];

__device__ __forceinline__ int searchsorted_inner_sm(const float* axis, float q, int n) {
    // searchsorted(axis[1:n-1], q, side='left') on smem-staged axis
    int lo = 0, hi = n - 2;
    while (lo < hi) {
        int mid = (lo + hi) >> 1;
        if (axis[1 + mid] < q) lo = mid + 1; else hi = mid;
    }
    return lo;
}

// Fused setup: axes staged in smem so the binary search is an LDS chain, not a
// DRAM-latency chain. One launch.
__global__ void precompute_fused(const float* __restrict__ xaxis,
                                 const float* __restrict__ yaxis,
                                 const float* __restrict__ xs,
                                 const float* __restrict__ ys,
                                 int n) {
    extern __shared__ float sax[];         // 2*n floats: sx | sy
    float* sx = sax;
    float* sy = sax + n;

    const int tid = threadIdx.x;
    const int k   = blockIdx.x * 256 + tid;

    for (int i = tid; i < n; i += 256) { sx[i] = xaxis[i]; sy[i] = yaxis[i]; }
    __syncthreads();

    if (k >= n) return;

    // ---- x direction ----
    {
        float q = xs[k];
        int I = searchsorted_inner_sm(sx, q, n);
        float x0 = sx[I];
        float x1 = sx[I + 1];
        int i2 = (I + 2 < n) ? I + 2 : n - 1;
        float x2 = sx[i2];
        float dx = x1 - x0;
        float t  = (q - x0) / dx;
        float t2 = t * t, t3 = t2 * t;
        float h0 = 1.0f - 3.0f * t2 + 2.0f * t3;
        float h1 = t - 2.0f * t2 + t3;
        float h2 = 3.0f * t2 - 2.0f * t3;
        float h3 = t3 - t2;
        float r  = dx / (x2 - x1);
        float4 w;
        w.x = h0 - h1;               // weight on S[I]
        w.y = h1 + h2 - h3 * r;      // weight on S[I+1]
        w.z = h3 * r;                // weight on S[I+2]
        w.w = __int_as_float(I);
        g_xw[k] = w;
    }
    // ---- y direction ----
    {
        float q = ys[k];
        int J = searchsorted_inner_sm(sy, q, n);
        float y0 = sy[J];
        float y1 = sy[J + 1];
        int j2 = (J + 2 < n) ? J + 2 : n - 1;
        float y2 = sy[j2];
        float dy = y1 - y0;
        float t  = (q - y0) / dy;
        float t2 = t * t, t3 = t2 * t;
        float h0 = 1.0f - 3.0f * t2 + 2.0f * t3;
        float h1 = t - 2.0f * t2 + t3;
        float h2 = 3.0f * t2 - 2.0f * t3;
        float h3 = t3 - t2;
        float r  = dy / (y2 - y1);
        float4 w;
        w.x = h0;        // weight on out[.., J]
        w.y = h2;        // weight on out[.., J+1]
        w.z = h1;        // weight on (S[J+1,k]-S[J,k])
        w.w = h3 * r;    // weight on (S[J+2,k]-S[J+1,k])
        g_yw[k] = w;
        g_yJ[k] = J;
    }
}

__device__ __forceinline__ float2 h2f(unsigned u) {
    __half2 h = *reinterpret_cast<__half2*>(&u);
    return __half22float2(h);
}

// ─────────────── Specialized N=1024, 4-batches-per-CTA, fp16 gather ─────────
// 512 threads/CTA, 2 k-slots per thread. One CTA handles output row `my` for
// 4 consecutive batches. Smem stores the gathered array rowC in fp16,
// batch-interleaved: 8 bytes per index hold all 4 batches, so each tap is one
// LDS.64 — half the gather bytes (and half the conflict replays) of fp32.
// The y-slope D term stays fp32 in registers, bounding the rounding error to
// the fp16 quantization of C (~1.5e-4 relative).
__global__ __launch_bounds__(512) void hermite2d_n1024_b4(
    const float* __restrict__ signal,
    float* __restrict__ out) {
    __shared__ __align__(8) uint2 rowCh[1024];   // 8 KB: (half2 b01, half2 b23)

    const int t  = threadIdx.x;            // 0..511
    const int bm = blockIdx.x;
    const int bq = bm >> 10;               // batch quad
    const int my = bm & 1023;

    const int    J  = g_yJ[my];
    const float4 yw = g_yw[my];

    // weight loads are independent of smem — issue before staging/barrier
    const float4 w0 = g_xw[t];
    const float4 w1 = g_xw[t + 512];

    const float* __restrict__ base0 = signal + (((size_t)(4 * bq + 0) << 10) + (size_t)J) * 1024u;
    const float* __restrict__ base1 = base0 + (1u << 20);
    const float* __restrict__ base2 = base0 + (2u << 20);
    const float* __restrict__ base3 = base0 + (3u << 20);

    float D[4][2];                         // [bb][j] coalesced y-slope term (fp32)

    #pragma unroll
    for (int j = 0; j < 2; j++) {
        const int k = t + 512 * j;
        float C0, C1, C2, C3;
        {
            float a = base0[k], c = base0[1024 + k], e = base0[2048 + k];
            C0 = yw.x * a + yw.y * c;
            D[0][j] = yw.z * (c - a) + yw.w * (e - c);
        }
        {
            float a = base1[k], c = base1[1024 + k], e = base1[2048 + k];
            C1 = yw.x * a + yw.y * c;
            D[1][j] = yw.z * (c - a) + yw.w * (e - c);
        }
        {
            float a = base2[k], c = base2[1024 + k], e = base2[2048 + k];
            C2 = yw.x * a + yw.y * c;
            D[2][j] = yw.z * (c - a) + yw.w * (e - c);
        }
        {
            float a = base3[k], c = base3[1024 + k], e = base3[2048 + k];
            C3 = yw.x * a + yw.y * c;
            D[3][j] = yw.z * (c - a) + yw.w * (e - c);
        }
        __half2 h01 = __floats2half2_rn(C0, C1);
        __half2 h23 = __floats2half2_rn(C2, C3);
        uint2 packed;
        packed.x = *reinterpret_cast<unsigned*>(&h01);
        packed.y = *reinterpret_cast<unsigned*>(&h23);
        rowCh[k] = packed;                 // STS.64, conflict-free
    }
    __syncthreads();

    float* __restrict__ o0 = out + (((size_t)(4 * bq + 0) << 10) + (size_t)my) * 1024u;
    float* __restrict__ o1 = o0 + (1u << 20);
    float* __restrict__ o2 = o0 + (2u << 20);
    float* __restrict__ o3 = o0 + (3u << 20);

    {
        const int k = t;
        const int I = __float_as_int(w0.w);
        const uint2 v0 = rowCh[I];         // LDS.64: taps for all 4 batches
        const uint2 v1 = rowCh[I + 1];
        const uint2 v2 = rowCh[I + 2];
        const float2 a0 = h2f(v0.x), b0 = h2f(v0.y);
        const float2 a1 = h2f(v1.x), b1 = h2f(v1.y);
        const float2 a2 = h2f(v2.x), b2 = h2f(v2.y);
        o0[k] = w0.x * a0.x + w0.y * a1.x + w0.z * a2.x + D[0][0];
        o1[k] = w0.x * a0.y + w0.y * a1.y + w0.z * a2.y + D[1][0];
        o2[k] = w0.x * b0.x + w0.y * b1.x + w0.z * b2.x + D[2][0];
        o3[k] = w0.x * b0.y + w0.y * b1.y + w0.z * b2.y + D[3][0];
    }
    {
        const int k = t + 512;
        const int I = __float_as_int(w1.w);
        const uint2 v0 = rowCh[I];
        const uint2 v1 = rowCh[I + 1];
        const uint2 v2 = rowCh[I + 2];
        const float2 a0 = h2f(v0.x), b0 = h2f(v0.y);
        const float2 a1 = h2f(v1.x), b1 = h2f(v1.y);
        const float2 a2 = h2f(v2.x), b2 = h2f(v2.y);
        o0[k] = w1.x * a0.x + w1.y * a1.x + w1.z * a2.x + D[0][1];
        o1[k] = w1.x * a0.y + w1.y * a1.y + w1.z * a2.y + D[1][1];
        o2[k] = w1.x * b0.x + w1.y * b1.x + w1.z * b2.x + D[2][1];
        o3[k] = w1.x * b0.y + w1.y * b1.y + w1.z * b2.y + D[3][1];
    }
}

// ─────────────── Specialized N=1024, 1 row per CTA (B % 4 != 0) ─────────────
__global__ __launch_bounds__(256) void hermite2d_n1024(
    const float* __restrict__ signal,
    float* __restrict__ out) {
    __shared__ float rowC[1024];

    const int t  = threadIdx.x;
    const int bm = blockIdx.x;
    const int b  = bm >> 10;
    const int my = bm & 1023;

    const int    J  = g_yJ[my];
    const float4 yw = g_yw[my];

    const float* __restrict__ base = signal + (((size_t)b << 10) + (size_t)J) * 1024u;

    float D[4];
    #pragma unroll
    for (int j = 0; j < 4; j++) {
        const int k = t + 256 * j;
        float a = base[k];
        float c = base[1024 + k];
        float e = base[2048 + k];
        rowC[k] = yw.x * a + yw.y * c;
        D[j]    = yw.z * (c - a) + yw.w * (e - c);
    }
    __syncthreads();

    float* __restrict__ orow = out + (((size_t)b << 10) + (size_t)my) * 1024u;
    #pragma unroll
    for (int j = 0; j < 4; j++) {
        const int k = t + 256 * j;
        const float4 w = g_xw[k];
        const int I = __float_as_int(w.w);
        orow[k] = w.x * rowC[I] + w.y * rowC[I + 1] + w.z * rowC[I + 2] + D[j];
    }
}

// ───────────────────────── Generic fallback (any n % 4 == 0) ─────────────────
__global__ __launch_bounds__(256) void hermite2d_generic(
    const float* __restrict__ signal,
    float* __restrict__ out,
    int n) {
    extern __shared__ float sm[];          // 2*n floats
    float* rowC = sm;
    float* rowD = sm + n;

    int bm = blockIdx.x;
    int b  = bm / n;
    int my = bm - b * n;

    int    J  = g_yJ[my];
    float4 yw = g_yw[my];

    const float* base = signal + ((size_t)b * n + J) * (size_t)n;
    int nv = n >> 2;
    const float4* srcJ  = reinterpret_cast<const float4*>(base);
    const float4* srcJ1 = reinterpret_cast<const float4*>(base + n);
    const float4* srcJ2 = reinterpret_cast<const float4*>(base + 2 * (size_t)n);
    float4* dstC = reinterpret_cast<float4*>(rowC);
    float4* dstD = reinterpret_cast<float4*>(rowD);
    for (int i = threadIdx.x; i < nv; i += blockDim.x) {
        float4 a = srcJ[i];
        float4 c = srcJ1[i];
        float4 e = srcJ2[i];
        float4 C, Dv;
        C.x = yw.x * a.x + yw.y * c.x;
        C.y = yw.x * a.y + yw.y * c.y;
        C.z = yw.x * a.z + yw.y * c.z;
        C.w = yw.x * a.w + yw.y * c.w;
        Dv.x = yw.z * (c.x - a.x) + yw.w * (e.x - c.x);
        Dv.y = yw.z * (c.y - a.y) + yw.w * (e.y - c.y);
        Dv.z = yw.z * (c.z - a.z) + yw.w * (e.z - c.z);
        Dv.w = yw.z * (c.w - a.w) + yw.w * (e.w - c.w);
        dstC[i] = C;
        dstD[i] = Dv;
    }
    __syncthreads();

    float* orow = out + ((size_t)b * n + my) * (size_t)n;
    for (int k = threadIdx.x; k < n; k += blockDim.x) {
        float4 xw = g_xw[k];
        int I = __float_as_int(xw.w);
        orow[k] = xw.x * rowC[I] + xw.y * rowC[I + 1] + xw.z * rowC[I + 2] + rowD[k];
    }
}

extern "C" void kernel_launch(void* const* d_in, const int* in_sizes, int n_in,
                              void* d_out, int out_size) {
    const float* xaxis  = (const float*)d_in[0];
    const float* yaxis  = (const float*)d_in[1];
    const float* signal = (const float*)d_in[2];
    const float* xs     = (const float*)d_in[3];
    const float* ys     = (const float*)d_in[4];
    float* out = (float*)d_out;

    int n = in_sizes[0];                 // N (square grid, Mx = My = N)
    int B = in_sizes[2] / (n * n);       // batch

    size_t smem_pre = 2 * (size_t)n * sizeof(float);
    precompute_fused<<<(n + 255) / 256, 256, smem_pre>>>(xaxis, yaxis, xs, ys, n);

    if (n == 1024 && (B % 4) == 0) {
        hermite2d_n1024_b4<<<(B / 4) * n, 512>>>(signal, out);
    } else if (n == 1024) {
        hermite2d_n1024<<<B * n, 256>>>(signal, out);
    } else {
        size_t smem = 2 * (size_t)n * sizeof(float);
        hermite2d_generic<<<B * n, 256, smem>>>(signal, out, n);
    }
}

// round 13
// speedup vs baseline: 1.4607x; 1.0042x over previous
#include <cuda_runtime.h>
#include <cuda_fp16.h>
#include <cstdint>

#define MAXN 4096

// Per-x-query: wa, wb, wc, bitcast(I)
__device__ float4 g_xw[MAXN];
// Per-y-query: h0, h2, h1, h3*ratio
__device__ float4 g_yw[MAXN];
__device__ int    g_yJ[MAXN];

__device__ __forceinline__ int searchsorted_inner_sm(const float* axis, float q, int n) {
    // searchsorted(axis[1:n-1], q, side='left') on smem-staged axis
    int lo = 0, hi = n - 2;
    while (lo < hi) {
        int mid = (lo + hi) >> 1;
        if (axis[1 + mid] < q) lo = mid + 1; else hi = mid;
    }
    return lo;
}

// Fused setup: axes staged in smem so the binary search is an LDS chain, not a
// DRAM-latency chain. One launch.
__global__ void precompute_fused(const float* __restrict__ xaxis,
                                 const float* __restrict__ yaxis,
                                 const float* __restrict__ xs,
                                 const float* __restrict__ ys,
                                 int n) {
    extern __shared__ float sax[];         // 2*n floats: sx | sy
    float* sx = sax;
    float* sy = sax + n;

    const int tid = threadIdx.x;
    const int k   = blockIdx.x * 256 + tid;

    for (int i = tid; i < n; i += 256) { sx[i] = xaxis[i]; sy[i] = yaxis[i]; }
    __syncthreads();

    if (k >= n) return;

    // ---- x direction ----
    {
        float q = xs[k];
        int I = searchsorted_inner_sm(sx, q, n);
        float x0 = sx[I];
        float x1 = sx[I + 1];
        int i2 = (I + 2 < n) ? I + 2 : n - 1;
        float x2 = sx[i2];
        float dx = x1 - x0;
        float t  = (q - x0) / dx;
        float t2 = t * t, t3 = t2 * t;
        float h0 = 1.0f - 3.0f * t2 + 2.0f * t3;
        float h1 = t - 2.0f * t2 + t3;
        float h2 = 3.0f * t2 - 2.0f * t3;
        float h3 = t3 - t2;
        float r  = dx / (x2 - x1);
        float4 w;
        w.x = h0 - h1;               // weight on S[I]
        w.y = h1 + h2 - h3 * r;      // weight on S[I+1]
        w.z = h3 * r;                // weight on S[I+2]
        w.w = __int_as_float(I);
        g_xw[k] = w;
    }
    // ---- y direction ----
    {
        float q = ys[k];
        int J = searchsorted_inner_sm(sy, q, n);
        float y0 = sy[J];
        float y1 = sy[J + 1];
        int j2 = (J + 2 < n) ? J + 2 : n - 1;
        float y2 = sy[j2];
        float dy = y1 - y0;
        float t  = (q - y0) / dy;
        float t2 = t * t, t3 = t2 * t;
        float h0 = 1.0f - 3.0f * t2 + 2.0f * t3;
        float h1 = t - 2.0f * t2 + t3;
        float h2 = 3.0f * t2 - 2.0f * t3;
        float h3 = t3 - t2;
        float r  = dy / (y2 - y1);
        float4 w;
        w.x = h0;        // weight on out[.., J]
        w.y = h2;        // weight on out[.., J+1]
        w.z = h1;        // weight on (S[J+1,k]-S[J,k])
        w.w = h3 * r;    // weight on (S[J+2,k]-S[J+1,k])
        g_yw[k] = w;
        g_yJ[k] = J;
    }
}

__device__ __forceinline__ float2 h2f(unsigned u) {
    __half2 h = *reinterpret_cast<__half2*>(&u);
    return __half22float2(h);
}

// ─────────────── Specialized N=1024, 4-batches-per-CTA, fp16 gather ─────────
// 512 threads/CTA, 2 k-slots per thread. One CTA handles output row `my` for
// 4 consecutive batches. Smem stores the gathered array rowC in fp16,
// batch-interleaved: 8 bytes per index hold all 4 batches, so each tap is one
// LDS.64 — half the gather bytes (and half the conflict replays) of fp32.
// The y-slope D term stays fp32 in registers, bounding the rounding error to
// the fp16 quantization of C (~1.5e-4 relative).
__global__ __launch_bounds__(512) void hermite2d_n1024_b4(
    const float* __restrict__ signal,
    float* __restrict__ out) {
    __shared__ __align__(8) uint2 rowCh[1024];   // 8 KB: (half2 b01, half2 b23)

    const int t  = threadIdx.x;            // 0..511
    const int bm = blockIdx.x;
    const int bq = bm >> 10;               // batch quad
    const int my = bm & 1023;

    const int    J  = g_yJ[my];
    const float4 yw = g_yw[my];

    // weight loads are independent of smem — issue before staging/barrier
    const float4 w0 = g_xw[t];
    const float4 w1 = g_xw[t + 512];

    const float* __restrict__ base0 = signal + (((size_t)(4 * bq + 0) << 10) + (size_t)J) * 1024u;
    const float* __restrict__ base1 = base0 + (1u << 20);
    const float* __restrict__ base2 = base0 + (2u << 20);
    const float* __restrict__ base3 = base0 + (3u << 20);

    float D[4][2];                         // [bb][j] coalesced y-slope term (fp32)

    #pragma unroll
    for (int j = 0; j < 2; j++) {
        const int k = t + 512 * j;
        float C0, C1, C2, C3;
        {
            float a = base0[k], c = base0[1024 + k], e = base0[2048 + k];
            C0 = yw.x * a + yw.y * c;
            D[0][j] = yw.z * (c - a) + yw.w * (e - c);
        }
        {
            float a = base1[k], c = base1[1024 + k], e = base1[2048 + k];
            C1 = yw.x * a + yw.y * c;
            D[1][j] = yw.z * (c - a) + yw.w * (e - c);
        }
        {
            float a = base2[k], c = base2[1024 + k], e = base2[2048 + k];
            C2 = yw.x * a + yw.y * c;
            D[2][j] = yw.z * (c - a) + yw.w * (e - c);
        }
        {
            float a = base3[k], c = base3[1024 + k], e = base3[2048 + k];
            C3 = yw.x * a + yw.y * c;
            D[3][j] = yw.z * (c - a) + yw.w * (e - c);
        }
        __half2 h01 = __floats2half2_rn(C0, C1);
        __half2 h23 = __floats2half2_rn(C2, C3);
        uint2 packed;
        packed.x = *reinterpret_cast<unsigned*>(&h01);
        packed.y = *reinterpret_cast<unsigned*>(&h23);
        rowCh[k] = packed;                 // STS.64, conflict-free
    }
    __syncthreads();

    float* __restrict__ o0 = out + (((size_t)(4 * bq + 0) << 10) + (size_t)my) * 1024u;
    float* __restrict__ o1 = o0 + (1u << 20);
    float* __restrict__ o2 = o0 + (2u << 20);
    float* __restrict__ o3 = o0 + (3u << 20);

    {
        const int k = t;
        const int I = __float_as_int(w0.w);
        const uint2 v0 = rowCh[I];         // LDS.64: taps for all 4 batches
        const uint2 v1 = rowCh[I + 1];
        const uint2 v2 = rowCh[I + 2];
        const float2 a0 = h2f(v0.x), b0 = h2f(v0.y);
        const float2 a1 = h2f(v1.x), b1 = h2f(v1.y);
        const float2 a2 = h2f(v2.x), b2 = h2f(v2.y);
        o0[k] = w0.x * a0.x + w0.y * a1.x + w0.z * a2.x + D[0][0];
        o1[k] = w0.x * a0.y + w0.y * a1.y + w0.z * a2.y + D[1][0];
        o2[k] = w0.x * b0.x + w0.y * b1.x + w0.z * b2.x + D[2][0];
        o3[k] = w0.x * b0.y + w0.y * b1.y + w0.z * b2.y + D[3][0];
    }
    {
        const int k = t + 512;
        const int I = __float_as_int(w1.w);
        const uint2 v0 = rowCh[I];
        const uint2 v1 = rowCh[I + 1];
        const uint2 v2 = rowCh[I + 2];
        const float2 a0 = h2f(v0.x), b0 = h2f(v0.y);
        const float2 a1 = h2f(v1.x), b1 = h2f(v1.y);
        const float2 a2 = h2f(v2.x), b2 = h2f(v2.y);
        o0[k] = w1.x * a0.x + w1.y * a1.x + w1.z * a2.x + D[0][1];
        o1[k] = w1.x * a0.y + w1.y * a1.y + w1.z * a2.y + D[1][1];
        o2[k] = w1.x * b0.x + w1.y * b1.x + w1.z * b2.x + D[2][1];
        o3[k] = w1.x * b0.y + w1.y * b1.y + w1.z * b2.y + D[3][1];
    }
}

// ─────────────── Specialized N=1024, 1 row per CTA (B % 4 != 0) ─────────────
__global__ __launch_bounds__(256) void hermite2d_n1024(
    const float* __restrict__ signal,
    float* __restrict__ out) {
    __shared__ float rowC[1024];

    const int t  = threadIdx.x;
    const int bm = blockIdx.x;
    const int b  = bm >> 10;
    const int my = bm & 1023;

    const int    J  = g_yJ[my];
    const float4 yw = g_yw[my];

    const float* __restrict__ base = signal + (((size_t)b << 10) + (size_t)J) * 1024u;

    float D[4];
    #pragma unroll
    for (int j = 0; j < 4; j++) {
        const int k = t + 256 * j;
        float a = base[k];
        float c = base[1024 + k];
        float e = base[2048 + k];
        rowC[k] = yw.x * a + yw.y * c;
        D[j]    = yw.z * (c - a) + yw.w * (e - c);
    }
    __syncthreads();

    float* __restrict__ orow = out + (((size_t)b << 10) + (size_t)my) * 1024u;
    #pragma unroll
    for (int j = 0; j < 4; j++) {
        const int k = t + 256 * j;
        const float4 w = g_xw[k];
        const int I = __float_as_int(w.w);
        orow[k] = w.x * rowC[I] + w.y * rowC[I + 1] + w.z * rowC[I + 2] + D[j];
    }
}

// ───────────────────────── Generic fallback (any n % 4 == 0) ─────────────────
__global__ __launch_bounds__(256) void hermite2d_generic(
    const float* __restrict__ signal,
    float* __restrict__ out,
    int n) {
    extern __shared__ float sm[];          // 2*n floats
    float* rowC = sm;
    float* rowD = sm + n;

    int bm = blockIdx.x;
    int b  = bm / n;
    int my = bm - b * n;

    int    J  = g_yJ[my];
    float4 yw = g_yw[my];

    const float* base = signal + ((size_t)b * n + J) * (size_t)n;
    int nv = n >> 2;
    const float4* srcJ  = reinterpret_cast<const float4*>(base);
    const float4* srcJ1 = reinterpret_cast<const float4*>(base + n);
    const float4* srcJ2 = reinterpret_cast<const float4*>(base + 2 * (size_t)n);
    float4* dstC = reinterpret_cast<float4*>(rowC);
    float4* dstD = reinterpret_cast<float4*>(rowD);
    for (int i = threadIdx.x; i < nv; i += blockDim.x) {
        float4 a = srcJ[i];
        float4 c = srcJ1[i];
        float4 e = srcJ2[i];
        float4 C, Dv;
        C.x = yw.x * a.x + yw.y * c.x;
        C.y = yw.x * a.y + yw.y * c.y;
        C.z = yw.x * a.z + yw.y * c.z;
        C.w = yw.x * a.w + yw.y * c.w;
        Dv.x = yw.z * (c.x - a.x) + yw.w * (e.x - c.x);
        Dv.y = yw.z * (c.y - a.y) + yw.w * (e.y - c.y);
        Dv.z = yw.z * (c.z - a.z) + yw.w * (e.z - c.z);
        Dv.w = yw.z * (c.w - a.w) + yw.w * (e.w - c.w);
        dstC[i] = C;
        dstD[i] = Dv;
    }
    __syncthreads();

    float* orow = out + ((size_t)b * n + my) * (size_t)n;
    for (int k = threadIdx.x; k < n; k += blockDim.x) {
        float4 xw = g_xw[k];
        int I = __float_as_int(xw.w);
        orow[k] = xw.x * rowC[I] + xw.y * rowC[I + 1] + xw.z * rowC[I + 2] + rowD[k];
    }
}

extern "C" void kernel_launch(void* const* d_in, const int* in_sizes, int n_in,
                              void* d_out, int out_size) {
    const float* xaxis  = (const float*)d_in[0];
    const float* yaxis  = (const float*)d_in[1];
    const float* signal = (const float*)d_in[2];
    const float* xs     = (const float*)d_in[3];
    const float* ys     = (const float*)d_in[4];
    float* out = (float*)d_out;

    int n = in_sizes[0];                 // N (square grid, Mx = My = N)
    int B = in_sizes[2] / (n * n);       // batch

    size_t smem_pre = 2 * (size_t)n * sizeof(float);
    precompute_fused<<<(n + 255) / 256, 256, smem_pre>>>(xaxis, yaxis, xs, ys, n);

    if (n == 1024 && (B % 4) == 0) {
        hermite2d_n1024_b4<<<(B / 4) * n, 512>>>(signal, out);
    } else if (n == 1024) {
        hermite2d_n1024<<<B * n, 256>>>(signal, out);
    } else {
        size_t smem = 2 * (size_t)n * sizeof(float);
        hermite2d_generic<<<B * n, 256, smem>>>(signal, out, n);
    }
}